// round 2
// baseline (speedup 1.0000x reference)
#include <cuda_runtime.h>
#include <cuda_bf16.h>

#define IMH 4096
#define IMW 4096
#define RAD 8
#define BX 128
#define OUT_W 112
#define CHUNK 32
#define SEGH 512
#define NSTRIPS ((IMW + OUT_W - 1) / OUT_W)   // 37
#define NSEG (IMH / SEGH)                     // 8
#define EPSF 1e-4f

// SMEM layout. Strides padded (129 / 113) for conflict-free row-indexed access.
struct SmemT {
    float  p_ring[17][BX + 1];     // last 17 rows of p (trailing edge of vertical window)
    float  i_ring[41][BX + 1];     // last 41 rows of i (trailing edge + center-i for HF)
    float4 vbuf[CHUNK][BX + 1];    // vertical box sums (i, p, pi, ii) for the chunk
    float  qbuf[CHUNK][OUT_W + 1]; // staged outputs for coalesced store
};

__global__ void __launch_bounds__(BX, 2)
gf_kernel(const float* __restrict__ gI, const float* __restrict__ gP,
          float* __restrict__ gQ)
{
    extern __shared__ unsigned char smem_raw[];
    SmemT& sm = *reinterpret_cast<SmemT*>(smem_raw);

    const int tid = threadIdx.x;
    const int ys  = blockIdx.y * SEGH;
    const int ch  = blockIdx.z;
    const int chOff = ch * IMH * IMW;
    const float* Ic = gI + chOff;
    const float* Pc = gP + chOff;
    float*       Qc = gQ + chOff;

    const int X0 = blockIdx.x * OUT_W;
    const int c  = X0 - RAD + tid;               // loaded column for this thread
    const bool cvalid = (c >= 0) && (c < IMW);

    float vs_i = 0.f, vs_p = 0.f, vs_pi = 0.f, vs_ii = 0.f;

    // ---- Warmup: rows ys-9 .. ys+7 into rings AND accumulator.
    // Sliding invariant: before the y=ys update, vs must hold sum over
    // rows [ys-9, ys+7] so that  vs += row(ys+8) - row(ys-9)  yields
    // sum[ys-8 .. ys+8]. (Out-of-image rows contribute 0.)
    for (int yl = ys - RAD - 1; yl <= ys + RAD - 1; ++yl) {
        float iv = 0.f, pv = 0.f;
        if (yl >= 0 && yl < IMH && cvalid) {
            iv = Ic[yl * IMW + c];
            pv = Pc[yl * IMW + c];
        }
        sm.p_ring[(yl + 34) % 17][tid] = pv;
        sm.i_ring[(yl + 41) % 41][tid] = iv;
        vs_i += iv; vs_p += pv; vs_pi += iv * pv; vs_ii += iv * iv;
    }

    // Ring slot counters (avoid per-iteration modulo)
    int s17  = (ys + RAD) % 17;   // leading & trailing p slot (17 apart -> same slot)
    int s41L = (ys + RAD) % 41;   // leading i slot
    int s41T = (ys + 32)  % 41;   // trailing i slot (row y-9)
    int y0m41 = ys % 41;          // chunk-base i-ring slot for HF center reads

    const int hr = tid & 31;      // HF: row within chunk (lane)
    const int hs = tid >> 5;      // HF: x-split (warp)
    const int xbase = RAD + 28 * hs;

    for (int ck = 0; ck < SEGH / CHUNK; ++ck) {
        const int y0 = ys + ck * CHUNK;

        // ---- V phase: vertical sliding box sums (thread-private columns) ----
        #pragma unroll 4
        for (int r = 0; r < CHUNK; ++r) {
            const int y  = y0 + r;
            const int yl = y + RAD;
            float iv = 0.f, pv = 0.f;
            if (yl < IMH && cvalid) {
                iv = Ic[yl * IMW + c];
                pv = Pc[yl * IMW + c];
            }
            const float pt = sm.p_ring[s17][tid];   // trailing p (row y-9), same slot
            const float it = sm.i_ring[s41T][tid];  // trailing i (row y-9)
            sm.p_ring[s17][tid]  = pv;
            sm.i_ring[s41L][tid] = iv;
            vs_i  += iv - it;
            vs_p  += pv - pt;
            vs_pi += iv * pv - it * pt;
            vs_ii += iv * iv - it * it;
            sm.vbuf[r][tid] = make_float4(vs_i, vs_p, vs_pi, vs_ii);
            s17  = (s17  + 1 == 17) ? 0 : s17  + 1;
            s41L = (s41L + 1 == 41) ? 0 : s41L + 1;
            s41T = (s41T + 1 == 41) ? 0 : s41T + 1;
        }
        __syncthreads();

        // ---- HF phase: horizontal sliding sums + guided-filter math ----
        {
            const int y = y0 + hr;
            int sy = y0m41 + hr; if (sy >= 41) sy -= 41;
            const int ny = min(y + RAD, IMH - 1) - max(y - RAD, 0) + 1;
            const float invNy = 1.0f / (float)ny;

            float4 h; h.x = h.y = h.z = h.w = 0.f;
            #pragma unroll
            for (int d = -RAD; d <= RAD; ++d) {
                float4 v = sm.vbuf[hr][xbase + d];
                h.x += v.x; h.y += v.y; h.z += v.z; h.w += v.w;
            }
            #pragma unroll 4
            for (int j = 0; j < 28; ++j) {
                const int x = xbase + j;
                if (j > 0) {
                    float4 a4 = sm.vbuf[hr][x + RAD];
                    float4 b4 = sm.vbuf[hr][x - RAD - 1];
                    h.x += a4.x - b4.x; h.y += a4.y - b4.y;
                    h.z += a4.z - b4.z; h.w += a4.w - b4.w;
                }
                const int gx = X0 + x - RAD;
                const int nx = min(gx + RAD, IMW - 1) - max(gx - RAD, 0) + 1;
                const float invNx = (nx == 17) ? (1.0f / 17.0f) : (1.0f / (float)nx);
                const float invN  = invNy * invNx;

                const float m_i  = h.x * invN;
                const float m_p  = h.y * invN;
                const float m_pi = h.z * invN;
                const float m_ii = h.w * invN;
                const float cov_ip = m_pi - m_p * m_i;
                const float cov_ii = m_ii - m_i * m_i;
                const float a = cov_ip / (cov_ii + EPSF);
                const float b = m_p - a * m_i;
                const float icen = sm.i_ring[sy][x];
                float q = a * icen + b;
                q = fminf(fmaxf(q, 0.0f), 1.0f);
                sm.qbuf[hr][x - RAD] = q;
            }
        }
        __syncthreads();

        // ---- Q phase: coalesced store ----
        if (tid < OUT_W && (X0 + tid) < IMW) {
            #pragma unroll 4
            for (int rr = 0; rr < CHUNK; ++rr) {
                Qc[(y0 + rr) * IMW + X0 + tid] = sm.qbuf[rr][tid];
            }
        }
        __syncthreads();   // protect vbuf/qbuf/i_ring before next chunk's V phase

        y0m41 += CHUNK; if (y0m41 >= 41) y0m41 -= 41;
    }
}

extern "C" void kernel_launch(void* const* d_in, const int* in_sizes, int n_in,
                              void* d_out, int out_size)
{
    const float* I = (const float*)d_in[0];
    const float* P = (const float*)d_in[1];
    float*       Q = (float*)d_out;

    cudaFuncSetAttribute(gf_kernel, cudaFuncAttributeMaxDynamicSharedMemorySize,
                         (int)sizeof(SmemT));

    dim3 grid(NSTRIPS, NSEG, 3);
    gf_kernel<<<grid, BX, sizeof(SmemT)>>>(I, P, Q);
}

// round 3
// speedup vs baseline: 1.2598x; 1.2598x over previous
#include <cuda_runtime.h>
#include <cuda_bf16.h>

#define IMH 4096
#define IMW 4096
#define RAD 8
#define BX 128
#define OUT_W 112
#define CHUNK 16
#define SEGH 512
#define NSTRIPS ((IMW + OUT_W - 1) / OUT_W)   // 37
#define NSEG (IMH / SEGH)                     // 8
#define EPSF 1e-4f
#define IRING 25
#define PRING 17

// Strides: 129 (odd mod 32 -> conflict-free for row-indexed access),
// 113 (odd) for qbuf.
struct SmemT {
    float p_ring[PRING][BX + 1];
    float i_ring[IRING][BX + 1];
    float vb_i [CHUNK][BX + 1];
    float vb_p [CHUNK][BX + 1];
    float vb_pi[CHUNK][BX + 1];
    float vb_ii[CHUNK][BX + 1];
    float qbuf[2][CHUNK][OUT_W + 1];
};

__global__ void __launch_bounds__(BX, 3)
gf_kernel(const float* __restrict__ gI, const float* __restrict__ gP,
          float* __restrict__ gQ)
{
    extern __shared__ unsigned char smem_raw[];
    SmemT& sm = *reinterpret_cast<SmemT*>(smem_raw);

    const int tid = threadIdx.x;
    const int ys  = blockIdx.y * SEGH;
    const int chOff = blockIdx.z * IMH * IMW;
    const float* Ic = gI + chOff;
    const float* Pc = gP + chOff;
    float*       Qc = gQ + chOff;

    const int X0 = blockIdx.x * OUT_W;
    const int c  = X0 - RAD + tid;
    const bool cvalid = (c >= 0) && (c < IMW);

    float vs_i = 0.f, vs_p = 0.f, vs_pi = 0.f, vs_ii = 0.f;

    // Warmup: rows ys-9 .. ys+7 into rings AND accumulator (17 rows).
    for (int yl = ys - RAD - 1; yl <= ys + RAD - 1; ++yl) {
        float iv = 0.f, pv = 0.f;
        if (yl >= 0 && yl < IMH && cvalid) {
            iv = Ic[yl * IMW + c];
            pv = Pc[yl * IMW + c];
        }
        sm.p_ring[(yl + 2 * PRING) % PRING][tid] = pv;
        sm.i_ring[(yl + 2 * IRING) % IRING][tid] = iv;
        vs_i += iv; vs_p += pv; vs_pi += iv * pv; vs_ii += iv * iv;
    }

    // Ring slot counters
    int s17  = (ys + RAD) % PRING;        // leading == trailing p slot
    int s25L = (ys + RAD) % IRING;        // leading i slot (row y+8)
    int s25T = (ys - RAD - 1 + IRING) % IRING; // trailing i slot (row y-9)
    int y0m  = ys % IRING;                // chunk-base i slot for HF reads

    const int hr = tid & 15;              // HF row within chunk
    const int hs = tid >> 4;              // HF x-split (8 splits x 14 cols)
    const int xbase = RAD + 14 * hs;

    for (int ck = 0; ck < SEGH / CHUNK; ++ck) {
        const int y0 = ys + ck * CHUNK;
        const int par = ck & 1;

        // ---- V phase: vertical sliding box sums ----
        #pragma unroll 8
        for (int r = 0; r < CHUNK; ++r) {
            const int yl = y0 + r + RAD;
            float iv = 0.f, pv = 0.f;
            if (yl < IMH && cvalid) {
                iv = Ic[yl * IMW + c];
                pv = Pc[yl * IMW + c];
            }
            const float pt = sm.p_ring[s17][tid];
            const float it = sm.i_ring[s25T][tid];
            sm.p_ring[s17][tid]  = pv;
            sm.i_ring[s25L][tid] = iv;
            vs_i  += iv - it;
            vs_p  += pv - pt;
            vs_pi += iv * pv - it * pt;
            vs_ii += iv * iv - it * it;
            sm.vb_i [r][tid] = vs_i;
            sm.vb_p [r][tid] = vs_p;
            sm.vb_pi[r][tid] = vs_pi;
            sm.vb_ii[r][tid] = vs_ii;
            s17  = (s17  + 1 == PRING) ? 0 : s17  + 1;
            s25L = (s25L + 1 == IRING) ? 0 : s25L + 1;
            s25T = (s25T + 1 == IRING) ? 0 : s25T + 1;
        }
        __syncthreads();

        // ---- HF phase ----
        {
            const int y = y0 + hr;
            int sy = y0m + hr; if (sy >= IRING) sy -= IRING;
            const int ny = min(y + RAD, IMH - 1) - max(y - RAD, 0) + 1;

            float hi = 0.f, hp = 0.f, hpi = 0.f, hii = 0.f;
            #pragma unroll
            for (int d = -RAD; d <= RAD; ++d) {
                hi  += sm.vb_i [hr][xbase + d];
                hp  += sm.vb_p [hr][xbase + d];
                hpi += sm.vb_pi[hr][xbase + d];
                hii += sm.vb_ii[hr][xbase + d];
            }
            #pragma unroll
            for (int j = 0; j < 14; ++j) {
                const int x = xbase + j;
                if (j > 0) {
                    hi  += sm.vb_i [hr][x + RAD] - sm.vb_i [hr][x - RAD - 1];
                    hp  += sm.vb_p [hr][x + RAD] - sm.vb_p [hr][x - RAD - 1];
                    hpi += sm.vb_pi[hr][x + RAD] - sm.vb_pi[hr][x - RAD - 1];
                    hii += sm.vb_ii[hr][x + RAD] - sm.vb_ii[hr][x - RAD - 1];
                }
                const int gx = X0 + x - RAD;
                const int nx = min(gx + RAD, IMW - 1) - max(gx - RAD, 0) + 1;
                const float invN = __fdividef(1.0f, (float)(ny * nx));

                const float m_i  = hi  * invN;
                const float m_p  = hp  * invN;
                const float m_pi = hpi * invN;
                const float m_ii = hii * invN;
                const float cov_ip = m_pi - m_p * m_i;
                const float cov_ii = m_ii - m_i * m_i;
                const float a = __fdividef(cov_ip, cov_ii + EPSF);
                const float b = m_p - a * m_i;
                const float icen = sm.i_ring[sy][x];
                float q = a * icen + b;
                q = fminf(fmaxf(q, 0.0f), 1.0f);
                sm.qbuf[par][hr][x - RAD] = q;
            }
        }
        __syncthreads();

        // ---- Q phase: coalesced store (no trailing barrier; qbuf is
        // double-buffered so next chunk's HF writes the other parity) ----
        if (tid < OUT_W && (X0 + tid) < IMW) {
            #pragma unroll 4
            for (int rr = 0; rr < CHUNK; ++rr) {
                Qc[(y0 + rr) * IMW + X0 + tid] = sm.qbuf[par][rr][tid];
            }
        }

        y0m += CHUNK; if (y0m >= IRING) y0m -= IRING;
    }
}

extern "C" void kernel_launch(void* const* d_in, const int* in_sizes, int n_in,
                              void* d_out, int out_size)
{
    const float* I = (const float*)d_in[0];
    const float* P = (const float*)d_in[1];
    float*       Q = (float*)d_out;

    cudaFuncSetAttribute(gf_kernel, cudaFuncAttributeMaxDynamicSharedMemorySize,
                         (int)sizeof(SmemT));

    dim3 grid(NSTRIPS, NSEG, 3);
    gf_kernel<<<grid, BX, sizeof(SmemT)>>>(I, P, Q);
}

// round 4
// speedup vs baseline: 1.4782x; 1.1734x over previous
#include <cuda_runtime.h>
#include <cuda_bf16.h>

#define IMH 4096
#define IMW 4096
#define RAD 8
#define BX 128
#define OUT_W 112
#define CHUNK 16
#define SEGH 512
#define NSTRIPS ((IMW + OUT_W - 1) / OUT_W)   // 37
#define NSEG (IMH / SEGH)                     // 8
#define EPSF 1e-4f
#define IRING 24

// 52.6 KB total -> 4 CTAs/SM. Strides 129/113 (odd mod 32) keep row-indexed
// accesses conflict-free.
struct SmemT {
    float i_ring[IRING][BX + 1];   // rows y0..y0+23 of i (HF center reads)
    float vb_i [CHUNK][BX + 1];    // vertical box sums
    float vb_p [CHUNK][BX + 1];
    float vb_pi[CHUNK][BX + 1];
    float vb_ii[CHUNK][BX + 1];
    float qbuf[CHUNK][OUT_W + 1];  // staged outputs (single-buffered)
};

__global__ void __launch_bounds__(BX, 4)
gf_kernel(const float* __restrict__ gI, const float* __restrict__ gP,
          float* __restrict__ gQ)
{
    extern __shared__ unsigned char smem_raw[];
    SmemT& sm = *reinterpret_cast<SmemT*>(smem_raw);

    const int tid = threadIdx.x;
    const int ys  = blockIdx.y * SEGH;
    const int chOff = blockIdx.z * IMH * IMW;
    const float* Ic = gI + chOff;
    const float* Pc = gP + chOff;
    float*       Qc = gQ + chOff;

    const int X0 = blockIdx.x * OUT_W;
    const int c  = X0 - RAD + tid;
    const bool cvalid = (c >= 0) && (c < IMW);

    float vs_i = 0.f, vs_p = 0.f, vs_pi = 0.f, vs_ii = 0.f;

    // Warmup: accumulate rows ys-9 .. ys+7 (17 rows); stash i rows into ring.
    // (Rows < ys land in slots later overwritten by chunk-0 V before HF reads.)
    for (int yl = ys - RAD - 1; yl <= ys + RAD - 1; ++yl) {
        float iv = 0.f, pv = 0.f;
        if (yl >= 0 && cvalid) {
            iv = Ic[yl * IMW + c];
            pv = Pc[yl * IMW + c];
        }
        sm.i_ring[(yl + 2 * IRING) % IRING][tid] = iv;
        vs_i += iv; vs_p += pv; vs_pi += iv * pv; vs_ii += iv * iv;
    }

    int sL  = (ys + RAD) % IRING;   // ring slot for leading row y+8
    int y0m = ys % IRING;           // chunk-base slot for HF reads

    const int hr = tid & 15;        // HF row within chunk
    const int hs = tid >> 4;        // HF x-split (8 splits x 14 cols)
    const int xbase = RAD + 14 * hs;

    for (int ck = 0; ck < SEGH / CHUNK; ++ck) {
        const int y0 = ys + ck * CHUNK;

        // ---- V phase: vertical sliding box sums; trailing edge re-read from
        // gmem (L2-resident: this CTA loaded those rows 17 iterations ago). ----
        #pragma unroll 4
        for (int r = 0; r < CHUNK; ++r) {
            const int yl = y0 + r + RAD;        // leading row
            const int yt = y0 + r - RAD - 1;    // trailing row
            float iv = 0.f, pv = 0.f, it = 0.f, pt = 0.f;
            if (yl < IMH && cvalid) {
                iv = Ic[yl * IMW + c];
                pv = Pc[yl * IMW + c];
            }
            if (yt >= 0 && cvalid) {
                it = Ic[yt * IMW + c];
                pt = Pc[yt * IMW + c];
            }
            sm.i_ring[sL][tid] = iv;
            vs_i  += iv - it;
            vs_p  += pv - pt;
            vs_pi += iv * pv - it * pt;
            vs_ii += iv * iv - it * it;
            sm.vb_i [r][tid] = vs_i;
            sm.vb_p [r][tid] = vs_p;
            sm.vb_pi[r][tid] = vs_pi;
            sm.vb_ii[r][tid] = vs_ii;
            sL = (sL + 1 == IRING) ? 0 : sL + 1;
        }
        __syncthreads();   // B1: vbuf + i_ring ready

        // ---- HF phase: horizontal sliding sums + guided-filter math ----
        {
            const int y = y0 + hr;
            int sy = y0m + hr; if (sy >= IRING) sy -= IRING;
            const int ny = min(y + RAD, IMH - 1) - max(y - RAD, 0) + 1;

            float hi = 0.f, hp = 0.f, hpi = 0.f, hii = 0.f;
            #pragma unroll
            for (int d = -RAD; d <= RAD; ++d) {
                hi  += sm.vb_i [hr][xbase + d];
                hp  += sm.vb_p [hr][xbase + d];
                hpi += sm.vb_pi[hr][xbase + d];
                hii += sm.vb_ii[hr][xbase + d];
            }
            #pragma unroll
            for (int j = 0; j < 14; ++j) {
                const int x = xbase + j;
                if (j > 0) {
                    hi  += sm.vb_i [hr][x + RAD] - sm.vb_i [hr][x - RAD - 1];
                    hp  += sm.vb_p [hr][x + RAD] - sm.vb_p [hr][x - RAD - 1];
                    hpi += sm.vb_pi[hr][x + RAD] - sm.vb_pi[hr][x - RAD - 1];
                    hii += sm.vb_ii[hr][x + RAD] - sm.vb_ii[hr][x - RAD - 1];
                }
                const int gx = X0 + x - RAD;
                const int nx = min(gx + RAD, IMW - 1) - max(gx - RAD, 0) + 1;
                const float invN = __fdividef(1.0f, (float)(ny * nx));

                const float m_i  = hi  * invN;
                const float m_p  = hp  * invN;
                const float m_pi = hpi * invN;
                const float m_ii = hii * invN;
                const float cov_ip = m_pi - m_p * m_i;
                const float cov_ii = m_ii - m_i * m_i;
                const float a = __fdividef(cov_ip, cov_ii + EPSF);
                const float b = m_p - a * m_i;
                const float icen = sm.i_ring[sy][x];
                float q = a * icen + b;
                q = fminf(fmaxf(q, 0.0f), 1.0f);
                sm.qbuf[hr][x - RAD] = q;
            }
        }
        __syncthreads();   // B2: qbuf ready, vbuf free

        // ---- Q phase: coalesced store. Runs concurrently with next chunk's
        // V phase (disjoint smem regions); next HF's qbuf writes are fenced
        // by the next B1. ----
        if (tid < OUT_W && (X0 + tid) < IMW) {
            #pragma unroll 4
            for (int rr = 0; rr < CHUNK; ++rr) {
                Qc[(y0 + rr) * IMW + X0 + tid] = sm.qbuf[rr][tid];
            }
        }

        y0m += CHUNK; if (y0m >= IRING) y0m -= IRING;
    }
}

extern "C" void kernel_launch(void* const* d_in, const int* in_sizes, int n_in,
                              void* d_out, int out_size)
{
    const float* I = (const float*)d_in[0];
    const float* P = (const float*)d_in[1];
    float*       Q = (float*)d_out;

    cudaFuncSetAttribute(gf_kernel, cudaFuncAttributeMaxDynamicSharedMemorySize,
                         (int)sizeof(SmemT));

    dim3 grid(NSTRIPS, NSEG, 3);
    gf_kernel<<<grid, BX, sizeof(SmemT)>>>(I, P, Q);
}